// round 15
// baseline (speedup 1.0000x reference)
#include <cuda_runtime.h>
#include <cuda_bf16.h>
#include <cstdint>

// x[8192,512] fp32, y[8192,512] fp32, out[8192,8192] fp32 (row-major).
#define DDIM   512
#define NROWS  8192
#define BM     128
#define BN     128
#define BK     64                   // 64 e4m3 elements (= 64 bytes) per k-iter
#define NK     (DDIM / BK)          // 8 k-iterations
#define STAGES 4

#define ROWB   80                   // padded row stride (64B data + 16B pad)
#define ABYTES (BM * ROWB)          // 10240
#define STAGE_BYTES (2 * ABYTES)    // 20480
#define SMEM_DYN (STAGES * STAGE_BYTES)  // 81920

__device__ __align__(16) uint8_t g_x8[NROWS * DDIM];
__device__ __align__(16) uint8_t g_y8[NROWS * DDIM];
__device__ float g_xsq[NROWS];
__device__ float g_ysq[NROWS];

static __device__ __forceinline__ uint32_t s2u(const void* p) {
    uint32_t a;
    asm("{ .reg .u64 t; cvta.to.shared.u64 t, %1; cvt.u32.u64 %0, t; }"
        : "=r"(a) : "l"(p));
    return a;
}

static __device__ __forceinline__ void cpa16(uint32_t s, const void* g) {
    asm volatile("cp.async.cg.shared.global [%0], [%1], 16;"
                 :: "r"(s), "l"(g) : "memory");
}

// pack 4 fp32 -> 4 e4m3 bytes (b0..b3 = v.x..v.w)
static __device__ __forceinline__ uint32_t f4_to_e4m3x4(float4 v) {
    uint16_t lo, hi;
    asm("cvt.rn.satfinite.e4m3x2.f32 %0, %1, %2;" : "=h"(lo) : "f"(v.y), "f"(v.x));
    asm("cvt.rn.satfinite.e4m3x2.f32 %0, %1, %2;" : "=h"(hi) : "f"(v.w), "f"(v.z));
    return ((uint32_t)hi << 16) | lo;
}

#define LDSM_X4(r0, r1, r2, r3, addr) \
    asm volatile("ldmatrix.sync.aligned.m8n8.x4.shared.b16 {%0,%1,%2,%3}, [%4];" \
                 : "=r"(r0), "=r"(r1), "=r"(r2), "=r"(r3) : "r"(addr))

// fp8 MMA: m16n8k32, e4m3 x e4m3 -> f32
#define MMA16832(d, a0, a1, a2, a3, b0, b1) \
    asm volatile("mma.sync.aligned.m16n8k32.row.col.f32.e4m3.e4m3.f32 " \
                 "{%0,%1,%2,%3}, {%4,%5,%6,%7}, {%8,%9}, {%0,%1,%2,%3};" \
                 : "+f"((d)[0]), "+f"((d)[1]), "+f"((d)[2]), "+f"((d)[3]) \
                 : "r"(a0), "r"(a1), "r"(a2), "r"(a3), "r"(b0), "r"(b1))

// ---------------------------------------------------------------------------
// Kernel 1: fp32 -> e4m3 + row squared norms (fp32). One warp per row.
// ---------------------------------------------------------------------------
__global__ __launch_bounds__(256)
void prep_kernel(const float* __restrict__ x, const float* __restrict__ y) {
    int warp = threadIdx.x >> 5;
    int lane = threadIdx.x & 31;
    int gr   = blockIdx.x * 8 + warp;       // 0..16383
    int row  = gr & (NROWS - 1);
    bool isy = gr >= NROWS;

    const float* src = isy ? y : x;
    uint8_t* dst = isy ? g_y8 : g_x8;
    const float4* p = reinterpret_cast<const float4*>(src + (size_t)row * DDIM);

    float s = 0.f;
#pragma unroll
    for (int i = 0; i < 4; i++) {
        float4 v = p[lane + 32 * i];
        s += v.x * v.x + v.y * v.y + v.z * v.z + v.w * v.w;
        uint32_t packed = f4_to_e4m3x4(v);
        *reinterpret_cast<uint32_t*>(dst + (size_t)row * DDIM + 4 * (lane + 32 * i)) = packed;
    }
#pragma unroll
    for (int o = 16; o > 0; o >>= 1) s += __shfl_xor_sync(0xFFFFFFFFu, s, o);
    if (lane == 0) (isy ? g_ysq : g_xsq)[row] = s;
}

// ---------------------------------------------------------------------------
// Kernel 2: e4m3 GEMM (128x128 CTA tile, 64x64 warp tile) + RBF epilogue.
// 4 warps: wm = wid>>1 (2 in M), wn = wid&1 (2 in N).
// Per k-iteration (64 K-elems): 2 x { 8 LDSM -> 32 MMAs (m16n8k32) }.
// Single-buffered fragments (32 regs) to stay under the 256-reg ceiling.
// ---------------------------------------------------------------------------
__global__ __launch_bounds__(128, 2)
void rbf_mma_kernel(float* __restrict__ O) {
    extern __shared__ char smem[];
    __shared__ float snx[BM];
    __shared__ float sny[BN];

    const uint32_t sd = s2u(smem);
    const int tid  = threadIdx.x;
    const int lane = tid & 31;
    const int wid  = tid >> 5;       // 0..3
    const int wm   = wid >> 1;       // 0..1
    const int wn   = wid & 1;        // 0..1
    const int bi   = blockIdx.y * BM;
    const int bj   = blockIdx.x * BN;

    const int r0 = tid >> 2, c0 = tid & 3;

    // ldmatrix byte offsets within a stage
    const uint32_t a_off = (uint32_t)((wm * 64 + (lane & 15)) * ROWB + (lane >> 4) * 16);
    const uint32_t b_off = (uint32_t)((wn * 64 + ((lane >> 4) << 3) + (lane & 7)) * ROWB
                                      + ((lane >> 3) & 1) * 16);

    auto load_stage = [&](int slot, int k0) {
        uint32_t sa = sd + slot * STAGE_BYTES;
        const uint8_t* gx = g_x8 + (size_t)bi * DDIM + k0;
        const uint8_t* gy = g_y8 + (size_t)bj * DDIM + k0;
#pragma unroll
        for (int t = 0; t < 4; t++) {
            int r = r0 + t * 32;
            cpa16(sa + r * ROWB + c0 * 16,          gx + (size_t)r * DDIM + c0 * 16);
            cpa16(sa + ABYTES + r * ROWB + c0 * 16, gy + (size_t)r * DDIM + c0 * 16);
        }
        asm volatile("cp.async.commit_group;" ::: "memory");
    };

    float d[128];
#pragma unroll
    for (int i = 0; i < 128; i++) d[i] = 0.f;

    // prologue: fill stages 0..2
    load_stage(0, 0);
    load_stage(1, BK);
    load_stage(2, 2 * BK);

    // norms staging
    snx[tid] = g_xsq[bi + tid];
    sny[tid] = g_ysq[bj + tid];

#pragma unroll 1
    for (int it = 0; it < NK; ++it) {
        if (it < NK - 2) asm volatile("cp.async.wait_group 2;" ::: "memory");
        else if (it == NK - 2) asm volatile("cp.async.wait_group 1;" ::: "memory");
        else asm volatile("cp.async.wait_group 0;" ::: "memory");
        __syncthreads();

        if (it + 3 < NK) load_stage((it + 3) & (STAGES - 1), (it + 3) * BK);

        const uint32_t sa  = sd + (it & (STAGES - 1)) * STAGE_BYTES;
        const uint32_t sbB = sa + ABYTES;

        // Two k32 slices, single-buffered fragments.
#pragma unroll
        for (int ks = 0; ks < 2; ks++) {
            uint32_t Af[4][4], Bf[4][4];
#pragma unroll
            for (int mt = 0; mt < 4; mt++)
                LDSM_X4(Af[mt][0], Af[mt][1], Af[mt][2], Af[mt][3],
                        sa + a_off + mt * 16 * ROWB + ks * 32);
#pragma unroll
            for (int ntp = 0; ntp < 4; ntp++)
                LDSM_X4(Bf[ntp][0], Bf[ntp][1], Bf[ntp][2], Bf[ntp][3],
                        sbB + b_off + ntp * 16 * ROWB + ks * 32);
#pragma unroll
            for (int mt = 0; mt < 4; mt++)
#pragma unroll
                for (int ntp = 0; ntp < 4; ntp++) {
                    MMA16832(&d[(mt * 8 + 2 * ntp) * 4],
                             Af[mt][0], Af[mt][1], Af[mt][2], Af[mt][3],
                             Bf[ntp][0], Bf[ntp][1]);
                    MMA16832(&d[(mt * 8 + 2 * ntp + 1) * 4],
                             Af[mt][0], Af[mt][1], Af[mt][2], Af[mt][3],
                             Bf[ntp][2], Bf[ntp][3]);
                }
        }
    }

    __syncthreads();  // pipeline drained; snx/sny visible

    // ---- fused epilogue: exp(-max(nx + ny - 2*dot, 0)), float2 stores ----
    const int rq = lane >> 2;
    const int cq = (lane & 3) * 2;
#pragma unroll
    for (int mt = 0; mt < 4; mt++) {
#pragma unroll
        for (int half = 0; half < 2; half++) {
            const int row = wm * 64 + mt * 16 + half * 8 + rq;
            const float nx = snx[row];
            float* orow = O + (size_t)(bi + row) * 8192 + bj;
#pragma unroll
            for (int n8 = 0; n8 < 8; n8++) {
                const int col = wn * 64 + n8 * 8 + cq;
                float d0 = d[(mt * 8 + n8) * 4 + half * 2 + 0];
                float d1 = d[(mt * 8 + n8) * 4 + half * 2 + 1];
                float s0 = fmaxf(fmaf(-2.f, d0, nx + sny[col]),     0.f);
                float s1 = fmaxf(fmaf(-2.f, d1, nx + sny[col + 1]), 0.f);
                float2 e = make_float2(__expf(-s0), __expf(-s1));
                *reinterpret_cast<float2*>(orow + col) = e;
            }
        }
    }
}

// ---------------------------------------------------------------------------
extern "C" void kernel_launch(void* const* d_in, const int* in_sizes, int n_in,
                              void* d_out, int out_size) {
    const float* x = (const float*)d_in[0];
    const float* y = (const float*)d_in[1];
    float* out = (float*)d_out;

    cudaFuncSetAttribute(rbf_mma_kernel,
                         cudaFuncAttributeMaxDynamicSharedMemorySize, SMEM_DYN);

    prep_kernel<<<NROWS * 2 / 8, 256>>>(x, y);
    rbf_mma_kernel<<<dim3(8192 / BN, 8192 / BM), 128, SMEM_DYN>>>(out);
}

// round 17
// speedup vs baseline: 1.0218x; 1.0218x over previous
#include <cuda_runtime.h>
#include <cuda_bf16.h>
#include <cstdint>

// x[8192,512] fp32, y[8192,512] fp32, out[8192,8192] fp32 (row-major).
#define DDIM   512
#define NROWS  8192
#define BM     128
#define BN     128
#define BK     64                    // 64 bf16 per k-iteration (128 bytes)
#define NK     (DDIM / BK)           // 8 k-iterations
#define STAGES 3

#define ROWB   144                   // 128B data + 16B pad: conflict-free ldmatrix
#define ABYTES (BM * ROWB)           // 18432
#define STAGE_BYTES (2 * ABYTES)     // 36864
#define SMEM_DYN (STAGES * STAGE_BYTES)   // 110592

__device__ __align__(16) __nv_bfloat16 g_xb[NROWS * DDIM];
__device__ __align__(16) __nv_bfloat16 g_yb[NROWS * DDIM];
__device__ float g_xsq[NROWS];
__device__ float g_ysq[NROWS];

static __device__ __forceinline__ uint32_t s2u(const void* p) {
    uint32_t a;
    asm("{ .reg .u64 t; cvta.to.shared.u64 t, %1; cvt.u32.u64 %0, t; }"
        : "=r"(a) : "l"(p));
    return a;
}

static __device__ __forceinline__ void cpa16(uint32_t s, const void* g) {
    asm volatile("cp.async.cg.shared.global [%0], [%1], 16;"
                 :: "r"(s), "l"(g) : "memory");
}

#define LDSM_X4(r0, r1, r2, r3, addr) \
    asm volatile("ldmatrix.sync.aligned.m8n8.x4.shared.b16 {%0,%1,%2,%3}, [%4];" \
                 : "=r"(r0), "=r"(r1), "=r"(r2), "=r"(r3) : "r"(addr))

#define MMA16816(d, a0, a1, a2, a3, b0, b1) \
    asm volatile("mma.sync.aligned.m16n8k16.row.col.f32.bf16.bf16.f32 " \
                 "{%0,%1,%2,%3}, {%4,%5,%6,%7}, {%8,%9}, {%0,%1,%2,%3};" \
                 : "+f"((d)[0]), "+f"((d)[1]), "+f"((d)[2]), "+f"((d)[3]) \
                 : "r"(a0), "r"(a1), "r"(a2), "r"(a3), "r"(b0), "r"(b1))

// ---------------------------------------------------------------------------
// Kernel 1: fp32 -> bf16 + row squared norms. One warp per row.
// ---------------------------------------------------------------------------
__global__ __launch_bounds__(256)
void prep_kernel(const float* __restrict__ x, const float* __restrict__ y) {
    int warp = threadIdx.x >> 5;
    int lane = threadIdx.x & 31;
    int gr   = blockIdx.x * 8 + warp;       // 0..16383
    int row  = gr & (NROWS - 1);
    bool isy = gr >= NROWS;

    const float* src = isy ? y : x;
    __nv_bfloat16* dst = isy ? g_yb : g_xb;
    const float4* p = reinterpret_cast<const float4*>(src + (size_t)row * DDIM);

    float s = 0.f;
#pragma unroll
    for (int i = 0; i < 4; i++) {
        float4 v = p[lane + 32 * i];
        s += v.x * v.x + v.y * v.y + v.z * v.z + v.w * v.w;
        __nv_bfloat162 lo = __floats2bfloat162_rn(v.x, v.y);
        __nv_bfloat162 hi = __floats2bfloat162_rn(v.z, v.w);
        uint2 u;
        u.x = *reinterpret_cast<uint32_t*>(&lo);
        u.y = *reinterpret_cast<uint32_t*>(&hi);
        *reinterpret_cast<uint2*>(dst + (size_t)row * DDIM + 4 * (lane + 32 * i)) = u;
    }
#pragma unroll
    for (int o = 16; o > 0; o >>= 1) s += __shfl_xor_sync(0xFFFFFFFFu, s, o);
    if (lane == 0) (isy ? g_ysq : g_xsq)[row] = s;
}

// ---------------------------------------------------------------------------
// Kernel 2: bf16 HMMA GEMM, 128x128 CTA tile, 64x64 warp tile, BK=64.
// 4 warps: wm = wid>>1 (2 in M), wn = wid&1 (2 in N).
// Per k-iteration (64 K-elems): ONE barrier, then 4 k16 slices of
// { 8 LDSM -> 32 MMAs }. 3-stage cp.async pipeline, prefetch distance 2.
// ---------------------------------------------------------------------------
__global__ __launch_bounds__(128, 2)
void rbf_mma_kernel(float* __restrict__ O) {
    extern __shared__ char smem[];
    __shared__ float snx[BM];
    __shared__ float sny[BN];

    const uint32_t sd = s2u(smem);
    const int tid  = threadIdx.x;
    const int lane = tid & 31;
    const int wid  = tid >> 5;       // 0..3
    const int wm   = wid >> 1;       // 0..1
    const int wn   = wid & 1;        // 0..1
    const int bi   = blockIdx.y * BM;
    const int bj   = blockIdx.x * BN;

    // cp.async per-thread indices: rows rA + 16*t, 16B chunk cA
    const int rA = tid >> 3;         // 0..15
    const int cA = tid & 7;          // 0..7

    // ldmatrix byte offsets within a stage
    const uint32_t a_off = (uint32_t)((wm * 64 + (lane & 15)) * ROWB + (lane >> 4) * 16);
    const uint32_t b_off = (uint32_t)((wn * 64 + ((lane >> 4) << 3) + (lane & 7)) * ROWB
                                      + ((lane >> 3) & 1) * 16);

    auto load_stage = [&](int slot, int k0) {
        uint32_t sa = sd + slot * STAGE_BYTES;
        const __nv_bfloat16* gx = g_xb + (size_t)bi * DDIM + k0;
        const __nv_bfloat16* gy = g_yb + (size_t)bj * DDIM + k0;
#pragma unroll
        for (int t = 0; t < 8; t++) {
            int r = rA + t * 16;
            cpa16(sa + r * ROWB + cA * 16,          gx + (size_t)r * DDIM + cA * 8);
            cpa16(sa + ABYTES + r * ROWB + cA * 16, gy + (size_t)r * DDIM + cA * 8);
        }
        asm volatile("cp.async.commit_group;" ::: "memory");
    };

    float d[128];
#pragma unroll
    for (int i = 0; i < 128; i++) d[i] = 0.f;

    // prologue: fill stages 0,1
    load_stage(0, 0);
    load_stage(1, BK);

    // norms staging
    snx[tid] = g_xsq[bi + tid];
    sny[tid] = g_ysq[bj + tid];

#pragma unroll 1
    for (int it = 0; it < NK; ++it) {
        if (it < NK - 2) asm volatile("cp.async.wait_group 1;" ::: "memory");
        else             asm volatile("cp.async.wait_group 0;" ::: "memory");
        __syncthreads();

        if (it + 2 < NK) load_stage((it + 2) % STAGES, (it + 2) * BK);

        const uint32_t sa  = sd + (it % STAGES) * STAGE_BYTES;
        const uint32_t sbB = sa + ABYTES;

        // Four k16 slices, single-buffered fragments.
#pragma unroll
        for (int ks = 0; ks < 4; ks++) {
            uint32_t Af[4][4], Bf[4][4];
#pragma unroll
            for (int mt = 0; mt < 4; mt++)
                LDSM_X4(Af[mt][0], Af[mt][1], Af[mt][2], Af[mt][3],
                        sa + a_off + mt * 16 * ROWB + ks * 32);
#pragma unroll
            for (int ntp = 0; ntp < 4; ntp++)
                LDSM_X4(Bf[ntp][0], Bf[ntp][1], Bf[ntp][2], Bf[ntp][3],
                        sbB + b_off + ntp * 16 * ROWB + ks * 32);
#pragma unroll
            for (int mt = 0; mt < 4; mt++)
#pragma unroll
                for (int ntp = 0; ntp < 4; ntp++) {
                    MMA16816(&d[(mt * 8 + 2 * ntp) * 4],
                             Af[mt][0], Af[mt][1], Af[mt][2], Af[mt][3],
                             Bf[ntp][0], Bf[ntp][1]);
                    MMA16816(&d[(mt * 8 + 2 * ntp + 1) * 4],
                             Af[mt][0], Af[mt][1], Af[mt][2], Af[mt][3],
                             Bf[ntp][2], Bf[ntp][3]);
                }
        }
    }

    __syncthreads();  // pipeline drained; snx/sny visible

    // ---- fused epilogue: exp(-max(nx + ny - 2*dot, 0)), float2 stores ----
    const int rq = lane >> 2;
    const int cq = (lane & 3) * 2;
#pragma unroll
    for (int mt = 0; mt < 4; mt++) {
#pragma unroll
        for (int half = 0; half < 2; half++) {
            const int row = wm * 64 + mt * 16 + half * 8 + rq;
            const float nx = snx[row];
            float* orow = O + (size_t)(bi + row) * 8192 + bj;
#pragma unroll
            for (int n8 = 0; n8 < 8; n8++) {
                const int col = wn * 64 + n8 * 8 + cq;
                float d0 = d[(mt * 8 + n8) * 4 + half * 2 + 0];
                float d1 = d[(mt * 8 + n8) * 4 + half * 2 + 1];
                float s0 = fmaxf(fmaf(-2.f, d0, nx + sny[col]),     0.f);
                float s1 = fmaxf(fmaf(-2.f, d1, nx + sny[col + 1]), 0.f);
                float2 e = make_float2(__expf(-s0), __expf(-s1));
                *reinterpret_cast<float2*>(orow + col) = e;
            }
        }
    }
}

// ---------------------------------------------------------------------------
extern "C" void kernel_launch(void* const* d_in, const int* in_sizes, int n_in,
                              void* d_out, int out_size) {
    const float* x = (const float*)d_in[0];
    const float* y = (const float*)d_in[1];
    float* out = (float*)d_out;

    cudaFuncSetAttribute(rbf_mma_kernel,
                         cudaFuncAttributeMaxDynamicSharedMemorySize, SMEM_DYN);

    prep_kernel<<<NROWS * 2 / 8, 256>>>(x, y);
    rbf_mma_kernel<<<dim3(8192 / BN, 8192 / BM), 128, SMEM_DYN>>>(out);
}